// round 6
// baseline (speedup 1.0000x reference)
#include <cuda_runtime.h>
#include <math.h>

#define B_   32
#define F_   256
#define T_   4096
#define NPB  (F_ * T_)
#define PADL 256

// blur tile
#define TF   16
#define TT   128
#define IH   (TF + 6)    // 22 input rows (halo 3)
#define IW   (TT + 6)    // 134 input cols
#define PH   (TF + 4)    // 20 p1 rows (halo 2)
#define PW   (TT + 4)    // 132 p1 cols
#define SW   136         // smem row stride (floats)

// Scratch: blurred field [B, F, T] fp32 (134 MB), per-batch min/max keys.
__device__ float    g_blur[(size_t)B_ * NPB];
__device__ unsigned g_mx1[B_], g_mn1[B_], g_mx2[B_], g_mn2[B_];

// Order-preserving float<->uint mapping for atomic min/max.
__device__ __forceinline__ unsigned fkey(float f) {
    unsigned u = __float_as_uint(f);
    return (u & 0x80000000u) ? ~u : (u | 0x80000000u);
}
__device__ __forceinline__ float funkey(unsigned k) {
    unsigned u = (k & 0x80000000u) ? (k & 0x7fffffffu) : ~k;
    return __uint_as_float(u);
}
// jnp.pad mode='reflect' index mapping (no edge duplication).
__device__ __forceinline__ int refl(int i, int n) {
    i = (i < 0) ? -i : i;
    i = (i >= n) ? (2 * n - 2 - i) : i;
    return i;
}

__global__ void init_k() {
    int i = threadIdx.x;
    if (i < B_) {
        g_mx1[i] = 0u;          g_mn1[i] = 0xFFFFFFFFu;
        g_mx2[i] = 0u;          g_mn2[i] = 0xFFFFFFFFu;
    }
}

// Stage A: per-batch min/max of the raw input. grid = (64, B_), 256 threads.
__global__ void minmax1_k(const float* __restrict__ in) {
    int b = blockIdx.y;
    const float4* p = (const float4*)(in + (size_t)b * NPB);
    int stride = gridDim.x * blockDim.x;
    int t = blockIdx.x * blockDim.x + threadIdx.x;
    float mx = -INFINITY, mn = INFINITY;
    for (int i = t; i < NPB / 4; i += stride) {
        float4 v = p[i];
        mx = fmaxf(mx, fmaxf(fmaxf(v.x, v.y), fmaxf(v.z, v.w)));
        mn = fminf(mn, fminf(fminf(v.x, v.y), fminf(v.z, v.w)));
    }
#pragma unroll
    for (int o = 16; o > 0; o >>= 1) {
        mx = fmaxf(mx, __shfl_xor_sync(0xffffffffu, mx, o));
        mn = fminf(mn, __shfl_xor_sync(0xffffffffu, mn, o));
    }
    __shared__ float smx[8], smn[8];
    int lane = threadIdx.x & 31, w = threadIdx.x >> 5;
    if (lane == 0) { smx[w] = mx; smn[w] = mn; }
    __syncthreads();
    if (threadIdx.x == 0) {
        for (int i = 1; i < (int)(blockDim.x >> 5); i++) {
            mx = fmaxf(mx, smx[i]); mn = fminf(mn, smn[i]);
        }
        atomicMax(&g_mx1[b], fkey(mx));
        atomicMin(&g_mn1[b], fkey(mn));
    }
}

// Stage B: fused peak1 -> normalize -> gaussian blur (freq conv then time conv),
// writes blurred field, per-batch min/max via one atomic pair per block.
// grid = (T/TT=32, F/TF=16, B), block = (32, 8) = 256 threads, 8 outputs/thread.
__global__ __launch_bounds__(256)
void blur_k(const float* __restrict__ in, float gw0, float gw1, float gw2) {
    __shared__ float f_s [IH][SW];   // raw input (halo 3), -inf outside the array
    __shared__ float p1_s[PH][SW];   // peak1-normalized (halo 2)
    __shared__ float tmp_s[TF][SW];  // freq-blurred (time halo 2)
    __shared__ float smx[8], smn[8];

    const int b   = blockIdx.z;
    const int fr0 = blockIdx.y * TF;
    const int t0  = blockIdx.x * TT;
    const int tx  = threadIdx.x;          // 0..31
    const int ty  = threadIdx.y;          // 0..7
    const int tid = ty * 32 + tx;
    const float* __restrict__ fin = in + (size_t)b * NPB;

    const bool int_f = (blockIdx.y > 0) && (blockIdx.y < gridDim.y - 1);
    const bool int_t = (blockIdx.x > 0) && (blockIdx.x < gridDim.x - 1);

    // ---- Load input tile with halo 3 ----
    if (int_f && int_t) {
#pragma unroll
        for (int r0 = 0; r0 < 3; r0++) {
            int r = ty + r0 * 8;
            if (r < IH) {
                const float* rp = fin + (size_t)(fr0 - 3 + r) * T_ + (t0 - 3);
#pragma unroll
                for (int c0 = 0; c0 < 5; c0++) {
                    int c = tx + c0 * 32;
                    if (c < IW) f_s[r][c] = rp[c];
                }
            }
        }
    } else {
#pragma unroll
        for (int r0 = 0; r0 < 3; r0++) {
            int r = ty + r0 * 8;
            if (r < IH) {
                int ar = fr0 - 3 + r;
                bool rok = (ar >= 0) && (ar < F_);
                const float* rp = fin + (size_t)(rok ? ar : 0) * T_;
#pragma unroll
                for (int c0 = 0; c0 < 5; c0++) {
                    int c = tx + c0 * 32;
                    if (c < IW) {
                        int ac = t0 - 3 + c;
                        float v = -INFINITY;
                        if (rok && ac >= 0 && ac < T_) v = rp[ac];
                        f_s[r][c] = v;
                    }
                }
            }
        }
    }
    __syncthreads();

    const float mn1  = funkey(g_mn1[b]);
    const float inv1 = 1.0f / (funkey(g_mx1[b]) - mn1);

    // ---- peak1 + normalize (halo-2 window; out-of-array slots written but never read) ----
#pragma unroll
    for (int r0 = 0; r0 < 3; r0++) {
        int r = ty + r0 * 8;
        if (r < PH) {
#pragma unroll
            for (int c0 = 0; c0 < 5; c0++) {
                int c = tx + c0 * 32;
                if (c < PW) {
                    float v = f_s[r + 1][c + 1];
                    bool m = (v >= f_s[r][c + 1]) && (v >= f_s[r + 2][c + 1]) &&
                             (v >= f_s[r + 1][c]) && (v >= f_s[r + 1][c + 2]);
                    p1_s[r][c] = m ? (v - mn1) * inv1 : 0.f;
                }
            }
        }
    }
    __syncthreads();

    // ---- Freq blur (taps symmetric: gw0,gw1,gw2,gw1,gw0) ----
    if (int_f) {
#pragma unroll
        for (int r0 = 0; r0 < 2; r0++) {
            int r = ty + r0 * 8;   // output row; taps at p1 slots r..r+4
#pragma unroll
            for (int c0 = 0; c0 < 5; c0++) {
                int c = tx + c0 * 32;
                if (c < PW) {
                    float s0 = p1_s[r][c] + p1_s[r + 4][c];
                    float s1 = p1_s[r + 1][c] + p1_s[r + 3][c];
                    tmp_s[r][c] = fmaf(gw0, s0, fmaf(gw1, s1, gw2 * p1_s[r + 2][c]));
                }
            }
        }
    } else {
#pragma unroll
        for (int r0 = 0; r0 < 2; r0++) {
            int r = ty + r0 * 8;
            int gy = fr0 + r;
            int rs0 = refl(gy - 2, F_) - (fr0 - 2);
            int rs1 = refl(gy - 1, F_) - (fr0 - 2);
            int rs2 = r + 2;
            int rs3 = refl(gy + 1, F_) - (fr0 - 2);
            int rs4 = refl(gy + 2, F_) - (fr0 - 2);
#pragma unroll
            for (int c0 = 0; c0 < 5; c0++) {
                int c = tx + c0 * 32;
                if (c < PW) {
                    float acc = gw0 * p1_s[rs0][c];
                    acc = fmaf(gw1, p1_s[rs1][c], acc);
                    acc = fmaf(gw2, p1_s[rs2][c], acc);
                    acc = fmaf(gw1, p1_s[rs3][c], acc);
                    acc = fmaf(gw0, p1_s[rs4][c], acc);
                    tmp_s[r][c] = acc;
                }
            }
        }
    }
    __syncthreads();

    // ---- Time blur -> global, fused per-batch min/max ----
    float bmx = -INFINITY, bmn = INFINITY;
    float* gout = g_blur + (size_t)b * NPB;
    if (int_t) {
#pragma unroll
        for (int r0 = 0; r0 < 2; r0++) {
            int r = ty + r0 * 8;
            float* orow = gout + (size_t)(fr0 + r) * T_ + t0;
#pragma unroll
            for (int c0 = 0; c0 < 4; c0++) {
                int c = tx + c0 * 32;    // taps at tmp slots c..c+4
                float s0 = tmp_s[r][c] + tmp_s[r][c + 4];
                float s1 = tmp_s[r][c + 1] + tmp_s[r][c + 3];
                float acc = fmaf(gw0, s0, fmaf(gw1, s1, gw2 * tmp_s[r][c + 2]));
                orow[c] = acc;
                bmx = fmaxf(bmx, acc); bmn = fminf(bmn, acc);
            }
        }
    } else {
#pragma unroll
        for (int r0 = 0; r0 < 2; r0++) {
            int r = ty + r0 * 8;
            float* orow = gout + (size_t)(fr0 + r) * T_ + t0;
#pragma unroll
            for (int c0 = 0; c0 < 4; c0++) {
                int c = tx + c0 * 32;
                int gx = t0 + c;
                int cs0 = refl(gx - 2, T_) - (t0 - 2);
                int cs1 = refl(gx - 1, T_) - (t0 - 2);
                int cs3 = refl(gx + 1, T_) - (t0 - 2);
                int cs4 = refl(gx + 2, T_) - (t0 - 2);
                float acc = gw0 * tmp_s[r][cs0];
                acc = fmaf(gw1, tmp_s[r][cs1], acc);
                acc = fmaf(gw2, tmp_s[r][c + 2], acc);
                acc = fmaf(gw1, tmp_s[r][cs3], acc);
                acc = fmaf(gw0, tmp_s[r][cs4], acc);
                orow[c] = acc;
                bmx = fmaxf(bmx, acc); bmn = fminf(bmn, acc);
            }
        }
    }

#pragma unroll
    for (int o = 16; o > 0; o >>= 1) {
        bmx = fmaxf(bmx, __shfl_xor_sync(0xffffffffu, bmx, o));
        bmn = fminf(bmn, __shfl_xor_sync(0xffffffffu, bmn, o));
    }
    int lane = tid & 31, w = tid >> 5;
    if (lane == 0) { smx[w] = bmx; smn[w] = bmn; }
    __syncthreads();
    if (tid == 0) {
        bmx = smx[0]; bmn = smn[0];
#pragma unroll
        for (int i = 1; i < 8; i++) {
            bmx = fmaxf(bmx, smx[i]); bmn = fminf(bmn, smn[i]);
        }
        atomicMax(&g_mx2[b], fkey(bmx));
        atomicMin(&g_mn2[b], fkey(bmn));
    }
}

// Stage D: peak2 + ordered compaction of the first PADL positives per batch.
// One 1024-thread block per batch; early exit once 256 entries are placed.
__global__ __launch_bounds__(1024)
void extract_k(float* __restrict__ out) {
    const int b = blockIdx.x;
    const float* bl = g_blur + (size_t)b * NPB;
    const float mn2 = funkey(g_mn2[b]);
    const float rng2 = funkey(g_mx2[b]) - mn2;
    float* ob = out + b * 3 * PADL;
    const int tid = threadIdx.x;
    const int lane = tid & 31, w = tid >> 5;

    for (int i = tid; i < 3 * PADL; i += 1024) ob[i] = 0.f;

    __shared__ unsigned s_wc[32];
    __shared__ unsigned s_tot;
    __shared__ unsigned s_base;
    if (tid == 0) s_base = 0;
    __syncthreads();

    for (int chunk = 0; chunk < NPB / 1024; chunk++) {
        int idx = chunk * 1024 + tid;
        int y = idx >> 12;          // idx / T_
        int x = idx & (T_ - 1);
        float v  = bl[idx];
        float nU = (y > 0)      ? bl[idx - T_] : -INFINITY;
        float nD = (y < F_ - 1) ? bl[idx + T_] : -INFINITY;
        float nL = (x > 0)      ? bl[idx - 1]  : -INFINITY;
        float nR = (x < T_ - 1) ? bl[idx + 1]  : -INFINITY;
        bool m = (v >= nU) && (v >= nD) && (v >= nL) && (v >= nR);
        float val = m ? __fdiv_rn(v - mn2, rng2) : 0.f;
        bool pred = val > 0.f;

        unsigned bal = __ballot_sync(0xffffffffu, pred);
        if (lane == 0) s_wc[w] = (unsigned)__popc(bal);
        __syncthreads();
        if (tid == 0) {
            unsigned run = 0;
#pragma unroll
            for (int i = 0; i < 32; i++) { unsigned c = s_wc[i]; s_wc[i] = run; run += c; }
            s_tot = run;
        }
        __syncthreads();
        unsigned base = s_base;
        unsigned tot  = s_tot;
        if (pred) {
            unsigned slot = base + s_wc[w] + (unsigned)__popc(bal & ((1u << lane) - 1u));
            if (slot < PADL) {
                ob[slot]            = (float)y / (float)F_;
                ob[PADL + slot]     = (float)x / (float)T_;
                ob[2 * PADL + slot] = val;
            }
        }
        __syncthreads();
        if (tid == 0) s_base = base + tot;
        if (base + tot >= PADL) break;   // uniform decision
        __syncthreads();
    }
}

extern "C" void kernel_launch(void* const* d_in, const int* in_sizes, int n_in,
                              void* d_out, int out_size) {
    const float* in = (const float*)d_in[0];
    float* out = (float*)d_out;

    // Gaussian weights, fp32, same formula as the reference.
    float g[5];
    float s = 0.f;
    for (int i = 0; i < 5; i++) {
        float c = (float)(i - 2);
        g[i] = expf(-0.5f * c * c);
    }
    for (int i = 0; i < 5; i++) s += g[i];
    for (int i = 0; i < 5; i++) g[i] = g[i] / s;

    init_k<<<1, 32>>>();
    minmax1_k<<<dim3(64, B_), 256>>>(in);
    blur_k<<<dim3(T_ / TT, F_ / TF, B_), dim3(32, 8)>>>(in, g[0], g[1], g[2]);
    extract_k<<<B_, 1024>>>(out);
}

// round 7
// speedup vs baseline: 1.4421x; 1.4421x over previous
#include <cuda_runtime.h>
#include <math.h>

#define B_   32
#define F_   256
#define T_   4096
#define NPB  (F_ * T_)
#define PADL 256

// blur tile: TF freq rows x TT time cols per block, 5 warps (160 threads).
// Warps overlap by 4 columns: warp w covers tmp columns [28w-2, 28w+30) rel. t0,
// producing 28 outputs (lanes 2..29). f_s spans cols [t0-3, t0+143).
#define TF   32
#define TT   128
#define NTHR 160
#define FH   (TF + 6)     // 38 input rows (halo 3)
#define FW   146          // input cols in smem
#define FST  148          // smem row stride

// Scratch: blurred field [B, F, T] fp32 (134 MB), per-batch min/max keys.
__device__ float    g_blur[(size_t)B_ * NPB];
__device__ unsigned g_mx1[B_], g_mn1[B_], g_mx2[B_], g_mn2[B_];

// Order-preserving float<->uint mapping for atomic min/max.
__device__ __forceinline__ unsigned fkey(float f) {
    unsigned u = __float_as_uint(f);
    return (u & 0x80000000u) ? ~u : (u | 0x80000000u);
}
__device__ __forceinline__ float funkey(unsigned k) {
    unsigned u = (k & 0x80000000u) ? (k & 0x7fffffffu) : ~k;
    return __uint_as_float(u);
}

__global__ void init_k() {
    int i = threadIdx.x;
    if (i < B_) {
        g_mx1[i] = 0u;          g_mn1[i] = 0xFFFFFFFFu;
        g_mx2[i] = 0u;          g_mn2[i] = 0xFFFFFFFFu;
    }
}

// Stage A: per-batch min/max of the raw input. grid = (64, B_), 256 threads.
__global__ void minmax1_k(const float* __restrict__ in) {
    int b = blockIdx.y;
    const float4* p = (const float4*)(in + (size_t)b * NPB);
    int stride = gridDim.x * blockDim.x;
    int t = blockIdx.x * blockDim.x + threadIdx.x;
    float mx = -INFINITY, mn = INFINITY;
    for (int i = t; i < NPB / 4; i += stride) {
        float4 v = p[i];
        mx = fmaxf(mx, fmaxf(fmaxf(v.x, v.y), fmaxf(v.z, v.w)));
        mn = fminf(mn, fminf(fminf(v.x, v.y), fminf(v.z, v.w)));
    }
#pragma unroll
    for (int o = 16; o > 0; o >>= 1) {
        mx = fmaxf(mx, __shfl_xor_sync(0xffffffffu, mx, o));
        mn = fminf(mn, __shfl_xor_sync(0xffffffffu, mn, o));
    }
    __shared__ float smx[8], smn[8];
    int lane = threadIdx.x & 31, w = threadIdx.x >> 5;
    if (lane == 0) { smx[w] = mx; smn[w] = mn; }
    __syncthreads();
    if (threadIdx.x == 0) {
        for (int i = 1; i < (int)(blockDim.x >> 5); i++) {
            mx = fmaxf(mx, smx[i]); mn = fminf(mn, smn[i]);
        }
        atomicMax(&g_mx1[b], fkey(mx));
        atomicMin(&g_mn1[b], fkey(mn));
    }
}

// Stage B: fused peak1 -> normalize -> freq blur (rolling registers) ->
// time blur (warp shuffles). One smem stage (raw input tile), one syncthreads.
// grid = (T/TT=32, F/TF=8, B), block = 160 threads (5 warps).
__global__ __launch_bounds__(NTHR)
void blur_k(const float* __restrict__ in, float gw0, float gw1, float gw2) {
    __shared__ float f_s[FH][FST];
    __shared__ float smx[5], smn[5];

    const int b    = blockIdx.z;
    const int fr0  = blockIdx.y * TF;
    const int t0   = blockIdx.x * TT;
    const int tid  = threadIdx.x;
    const int lane = tid & 31;
    const int w    = tid >> 5;
    const float* __restrict__ fin = in + (size_t)b * NPB;

    const bool int_f = (blockIdx.y > 0) && (blockIdx.y < gridDim.y - 1);
    const bool int_t = (blockIdx.x > 0) && (blockIdx.x < gridDim.x - 1);

    // ---- Load input tile (halo 3); -inf outside the array (SAME-pad for peak test) ----
    if (tid < FW) {
        int ac = t0 - 3 + tid;
        if (int_f && int_t) {
            const float* cp = fin + (size_t)(fr0 - 3) * T_ + ac;
#pragma unroll
            for (int r = 0; r < FH; r++) f_s[r][tid] = cp[(size_t)r * T_];
        } else {
            bool cok = (ac >= 0) && (ac < T_);
#pragma unroll
            for (int r = 0; r < FH; r++) {
                int ar = fr0 - 3 + r;
                float v = -INFINITY;
                if (cok && ar >= 0 && ar < F_) v = fin[(size_t)ar * T_ + ac];
                f_s[r][tid] = v;
            }
        }
    }
    __syncthreads();

    const float mn1  = funkey(g_mn1[b]);
    const float inv1 = 1.0f / (funkey(g_mx1[b]) - mn1);
    const bool topE = (fr0 == 0);
    const bool botE = (fr0 == F_ - TF);

    // ---- Rolling peak1 + freq blur: thread owns tmp column ct = t0 + 28w + lane - 2 ----
    const int ci = 28 * w + lane + 1;        // f_s column index of ct
    float tmp[TF];
    float ring[5];
    float fa = f_s[0][ci];                                        // f row pr-1 center
    float tl = f_s[1][ci - 1], tc = f_s[1][ci], tr = f_s[1][ci + 1];  // f row pr triple
#pragma unroll
    for (int s = 0; s < TF + 4; s++) {       // p1 row pr = s - 2 in [-2, TF+1]
        float nl = f_s[s + 2][ci - 1], nc = f_s[s + 2][ci], nr = f_s[s + 2][ci + 1];
        bool m = (tc >= fa) && (tc >= nc) && (tc >= tl) && (tc >= tr);
        ring[s % 5] = m ? (tc - mn1) * inv1 : 0.f;
        if (s >= 4) {
            const int r = s - 4;             // output row (p1 rows r-2..r+2 in ring)
            float p0  = ring[(s + 1) % 5];   // r-2
            float p1v = ring[(s + 2) % 5];   // r-1
            float p2  = ring[(s + 3) % 5];   // r
            float p3  = ring[(s + 4) % 5];   // r+1
            float p4  = ring[ s      % 5];   // r+2
            float acc;
            if (topE && r == 0)
                acc = fmaf(2.f * gw1, p3, fmaf(2.f * gw0, p4, gw2 * p2));
            else if (topE && r == 1)
                acc = fmaf(gw1, p1v, fmaf(gw0 + gw2, p2, fmaf(gw1, p3, gw0 * p4)));
            else if (botE && r == TF - 2)
                acc = fmaf(gw0, p0, fmaf(gw1, p1v, fmaf(gw2 + gw0, p2, gw1 * p3)));
            else if (botE && r == TF - 1)
                acc = fmaf(2.f * gw0, p0, fmaf(2.f * gw1, p1v, gw2 * p2));
            else {
                float s0 = p0 + p4, s1 = p1v + p3;
                acc = fmaf(gw0, s0, fmaf(gw1, s1, gw2 * p2));
            }
            tmp[r] = acc;
        }
        fa = tc; tl = nl; tc = nc; tr = nr;
    }

    // ---- Time blur via shuffles; lanes 2..29 produce outputs ----
    const int ocol = 28 * w + lane - 2;
    const bool out_ok = (lane >= 2) && (lane <= 29) && (ocol < TT);
    const int gx = t0 + ocol;
    float bmx = -INFINITY, bmn = INFINITY;
    float* op = g_blur + (size_t)b * NPB + (size_t)fr0 * T_ + gx;
#pragma unroll
    for (int r = 0; r < TF; r++) {
        float v   = tmp[r];
        float vm1 = __shfl_up_sync(0xffffffffu, v, 1);
        float vm2 = __shfl_up_sync(0xffffffffu, v, 2);
        float vp1 = __shfl_down_sync(0xffffffffu, v, 1);
        float vp2 = __shfl_down_sync(0xffffffffu, v, 2);
        if (out_ok) {
            float acc;
            if (gx == 0)
                acc = fmaf(2.f * gw1, vp1, fmaf(2.f * gw0, vp2, gw2 * v));
            else if (gx == 1)
                acc = fmaf(gw1, vm1, fmaf(gw0 + gw2, v, fmaf(gw1, vp1, gw0 * vp2)));
            else if (gx == T_ - 2)
                acc = fmaf(gw0, vm2, fmaf(gw1, vm1, fmaf(gw2 + gw0, v, gw1 * vp1)));
            else if (gx == T_ - 1)
                acc = fmaf(2.f * gw0, vm2, fmaf(2.f * gw1, vm1, gw2 * v));
            else {
                float s0 = vm2 + vp2, s1 = vm1 + vp1;
                acc = fmaf(gw0, s0, fmaf(gw1, s1, gw2 * v));
            }
            op[(size_t)r * T_] = acc;
            bmx = fmaxf(bmx, acc); bmn = fminf(bmn, acc);
        }
    }

    // ---- Fused per-batch min/max of the blurred field ----
#pragma unroll
    for (int o = 16; o > 0; o >>= 1) {
        bmx = fmaxf(bmx, __shfl_xor_sync(0xffffffffu, bmx, o));
        bmn = fminf(bmn, __shfl_xor_sync(0xffffffffu, bmn, o));
    }
    if (lane == 0) { smx[w] = bmx; smn[w] = bmn; }
    __syncthreads();
    if (tid == 0) {
        bmx = smx[0]; bmn = smn[0];
#pragma unroll
        for (int i = 1; i < 5; i++) {
            bmx = fmaxf(bmx, smx[i]); bmn = fminf(bmn, smn[i]);
        }
        atomicMax(&g_mx2[b], fkey(bmx));
        atomicMin(&g_mn2[b], fkey(bmn));
    }
}

// Stage D: peak2 + ordered compaction of the first PADL positives per batch.
// One 1024-thread block per batch; early exit once 256 entries are placed.
__global__ __launch_bounds__(1024)
void extract_k(float* __restrict__ out) {
    const int b = blockIdx.x;
    const float* bl = g_blur + (size_t)b * NPB;
    const float mn2 = funkey(g_mn2[b]);
    const float rng2 = funkey(g_mx2[b]) - mn2;
    float* ob = out + b * 3 * PADL;
    const int tid = threadIdx.x;
    const int lane = tid & 31, w = tid >> 5;

    for (int i = tid; i < 3 * PADL; i += 1024) ob[i] = 0.f;

    __shared__ unsigned s_wc[32];
    __shared__ unsigned s_tot;
    __shared__ unsigned s_base;
    if (tid == 0) s_base = 0;
    __syncthreads();

    for (int chunk = 0; chunk < NPB / 1024; chunk++) {
        int idx = chunk * 1024 + tid;
        int y = idx >> 12;          // idx / T_
        int x = idx & (T_ - 1);
        float v  = bl[idx];
        float nU = (y > 0)      ? bl[idx - T_] : -INFINITY;
        float nD = (y < F_ - 1) ? bl[idx + T_] : -INFINITY;
        float nL = (x > 0)      ? bl[idx - 1]  : -INFINITY;
        float nR = (x < T_ - 1) ? bl[idx + 1]  : -INFINITY;
        bool m = (v >= nU) && (v >= nD) && (v >= nL) && (v >= nR);
        float val = m ? __fdiv_rn(v - mn2, rng2) : 0.f;
        bool pred = val > 0.f;

        unsigned bal = __ballot_sync(0xffffffffu, pred);
        if (lane == 0) s_wc[w] = (unsigned)__popc(bal);
        __syncthreads();
        if (tid == 0) {
            unsigned run = 0;
#pragma unroll
            for (int i = 0; i < 32; i++) { unsigned c = s_wc[i]; s_wc[i] = run; run += c; }
            s_tot = run;
        }
        __syncthreads();
        unsigned base = s_base;
        unsigned tot  = s_tot;
        if (pred) {
            unsigned slot = base + s_wc[w] + (unsigned)__popc(bal & ((1u << lane) - 1u));
            if (slot < PADL) {
                ob[slot]            = (float)y / (float)F_;
                ob[PADL + slot]     = (float)x / (float)T_;
                ob[2 * PADL + slot] = val;
            }
        }
        __syncthreads();
        if (tid == 0) s_base = base + tot;
        if (base + tot >= PADL) break;   // uniform decision
        __syncthreads();
    }
}

extern "C" void kernel_launch(void* const* d_in, const int* in_sizes, int n_in,
                              void* d_out, int out_size) {
    const float* in = (const float*)d_in[0];
    float* out = (float*)d_out;

    // Gaussian weights, fp32, same formula as the reference.
    float g[5];
    float s = 0.f;
    for (int i = 0; i < 5; i++) {
        float c = (float)(i - 2);
        g[i] = expf(-0.5f * c * c);
    }
    for (int i = 0; i < 5; i++) s += g[i];
    for (int i = 0; i < 5; i++) g[i] = g[i] / s;

    init_k<<<1, 32>>>();
    minmax1_k<<<dim3(64, B_), 256>>>(in);
    blur_k<<<dim3(T_ / TT, F_ / TF, B_), NTHR>>>(in, g[0], g[1], g[2]);
    extract_k<<<B_, 1024>>>(out);
}

// round 8
// speedup vs baseline: 1.4463x; 1.0029x over previous
#include <cuda_runtime.h>
#include <math.h>

#define B_   32
#define F_   256
#define T_   4096
#define NPB  (F_ * T_)
#define PADL 256

// blur tile: TF freq rows x TT time cols per block, 5 warps (160 threads).
// Warps overlap by 4 columns: warp w covers tmp columns [28w-2, 28w+30) rel. t0,
// producing 28 outputs (lanes 2..29). f_s spans cols [t0-3, t0+143).
#define TF   32
#define TT   128
#define NTHR 160
#define FH   (TF + 6)     // 38 input rows (halo 3)
#define FW   146          // input cols in smem
#define FST  148          // smem row stride

// Scratch: blurred field [B, F, T] fp32 (134 MB), per-batch min/max keys.
__device__ float    g_blur[(size_t)B_ * NPB];
__device__ unsigned g_mx1[B_], g_mn1[B_], g_mx2[B_], g_mn2[B_];

// Order-preserving float<->uint mapping for atomic min/max.
__device__ __forceinline__ unsigned fkey(float f) {
    unsigned u = __float_as_uint(f);
    return (u & 0x80000000u) ? ~u : (u | 0x80000000u);
}
__device__ __forceinline__ float funkey(unsigned k) {
    unsigned u = (k & 0x80000000u) ? (k & 0x7fffffffu) : ~k;
    return __uint_as_float(u);
}

__global__ void init_k() {
    int i = threadIdx.x;
    if (i < B_) {
        g_mx1[i] = 0u;          g_mn1[i] = 0xFFFFFFFFu;
        g_mx2[i] = 0u;          g_mn2[i] = 0xFFFFFFFFu;
    }
}

// Stage A: per-batch min/max of the raw input. grid = (64, B_), 256 threads.
__global__ void minmax1_k(const float* __restrict__ in) {
    int b = blockIdx.y;
    const float4* p = (const float4*)(in + (size_t)b * NPB);
    int stride = gridDim.x * blockDim.x;
    int t = blockIdx.x * blockDim.x + threadIdx.x;
    float mx = -INFINITY, mn = INFINITY;
    for (int i = t; i < NPB / 4; i += stride) {
        float4 v = p[i];
        mx = fmaxf(mx, fmaxf(fmaxf(v.x, v.y), fmaxf(v.z, v.w)));
        mn = fminf(mn, fminf(fminf(v.x, v.y), fminf(v.z, v.w)));
    }
#pragma unroll
    for (int o = 16; o > 0; o >>= 1) {
        mx = fmaxf(mx, __shfl_xor_sync(0xffffffffu, mx, o));
        mn = fminf(mn, __shfl_xor_sync(0xffffffffu, mn, o));
    }
    __shared__ float smx[8], smn[8];
    int lane = threadIdx.x & 31, w = threadIdx.x >> 5;
    if (lane == 0) { smx[w] = mx; smn[w] = mn; }
    __syncthreads();
    if (threadIdx.x == 0) {
        for (int i = 1; i < (int)(blockDim.x >> 5); i++) {
            mx = fmaxf(mx, smx[i]); mn = fminf(mn, smn[i]);
        }
        atomicMax(&g_mx1[b], fkey(mx));
        atomicMin(&g_mn1[b], fkey(mn));
    }
}

// Stage B: fused peak1 -> normalize -> freq blur (rolling registers) ->
// time blur (warp shuffles). One smem stage (raw input tile), one syncthreads.
// grid = (T/TT=32, F/TF=8, B), block = 160 threads (5 warps).
__global__ __launch_bounds__(NTHR)
void blur_k(const float* __restrict__ in, float gw0, float gw1, float gw2) {
    __shared__ float f_s[FH][FST];
    __shared__ float smx[5], smn[5];

    const int b    = blockIdx.z;
    const int fr0  = blockIdx.y * TF;
    const int t0   = blockIdx.x * TT;
    const int tid  = threadIdx.x;
    const int lane = tid & 31;
    const int w    = tid >> 5;
    const float* __restrict__ fin = in + (size_t)b * NPB;

    const bool int_f = (blockIdx.y > 0) && (blockIdx.y < gridDim.y - 1);
    const bool int_t = (blockIdx.x > 0) && (blockIdx.x < gridDim.x - 1);

    // ---- Load input tile (halo 3); -inf outside the array (SAME-pad for peak test) ----
    if (tid < FW) {
        int ac = t0 - 3 + tid;
        if (int_f && int_t) {
            const float* cp = fin + (size_t)(fr0 - 3) * T_ + ac;
#pragma unroll
            for (int r = 0; r < FH; r++) f_s[r][tid] = cp[(size_t)r * T_];
        } else {
            bool cok = (ac >= 0) && (ac < T_);
#pragma unroll
            for (int r = 0; r < FH; r++) {
                int ar = fr0 - 3 + r;
                float v = -INFINITY;
                if (cok && ar >= 0 && ar < F_) v = fin[(size_t)ar * T_ + ac];
                f_s[r][tid] = v;
            }
        }
    }
    __syncthreads();

    const float mn1  = funkey(g_mn1[b]);
    const float inv1 = 1.0f / (funkey(g_mx1[b]) - mn1);
    const bool topE = (fr0 == 0);
    const bool botE = (fr0 == F_ - TF);

    // ---- Rolling peak1 + freq blur: thread owns tmp column ct = t0 + 28w + lane - 2 ----
    const int ci = 28 * w + lane + 1;        // f_s column index of ct
    float tmp[TF];
    float ring[5];
    float fa = f_s[0][ci];                                        // f row pr-1 center
    float tl = f_s[1][ci - 1], tc = f_s[1][ci], tr = f_s[1][ci + 1];  // f row pr triple
#pragma unroll
    for (int s = 0; s < TF + 4; s++) {       // p1 row pr = s - 2 in [-2, TF+1]
        float nl = f_s[s + 2][ci - 1], nc = f_s[s + 2][ci], nr = f_s[s + 2][ci + 1];
        bool m = (tc >= fa) && (tc >= nc) && (tc >= tl) && (tc >= tr);
        ring[s % 5] = m ? (tc - mn1) * inv1 : 0.f;
        if (s >= 4) {
            const int r = s - 4;             // output row (p1 rows r-2..r+2 in ring)
            float p0  = ring[(s + 1) % 5];   // r-2
            float p1v = ring[(s + 2) % 5];   // r-1
            float p2  = ring[(s + 3) % 5];   // r
            float p3  = ring[(s + 4) % 5];   // r+1
            float p4  = ring[ s      % 5];   // r+2
            float acc;
            if (topE && r == 0)
                acc = fmaf(2.f * gw1, p3, fmaf(2.f * gw0, p4, gw2 * p2));
            else if (topE && r == 1)
                acc = fmaf(gw1, p1v, fmaf(gw0 + gw2, p2, fmaf(gw1, p3, gw0 * p4)));
            else if (botE && r == TF - 2)
                acc = fmaf(gw0, p0, fmaf(gw1, p1v, fmaf(gw2 + gw0, p2, gw1 * p3)));
            else if (botE && r == TF - 1)
                acc = fmaf(2.f * gw0, p0, fmaf(2.f * gw1, p1v, gw2 * p2));
            else {
                float s0 = p0 + p4, s1 = p1v + p3;
                acc = fmaf(gw0, s0, fmaf(gw1, s1, gw2 * p2));
            }
            tmp[r] = acc;
        }
        fa = tc; tl = nl; tc = nc; tr = nr;
    }

    // ---- Time blur via shuffles; lanes 2..29 produce outputs ----
    const int ocol = 28 * w + lane - 2;
    const bool out_ok = (lane >= 2) && (lane <= 29) && (ocol < TT);
    const int gx = t0 + ocol;
    float bmx = -INFINITY, bmn = INFINITY;
    float* op = g_blur + (size_t)b * NPB + (size_t)fr0 * T_ + gx;
#pragma unroll
    for (int r = 0; r < TF; r++) {
        float v   = tmp[r];
        float vm1 = __shfl_up_sync(0xffffffffu, v, 1);
        float vm2 = __shfl_up_sync(0xffffffffu, v, 2);
        float vp1 = __shfl_down_sync(0xffffffffu, v, 1);
        float vp2 = __shfl_down_sync(0xffffffffu, v, 2);
        if (out_ok) {
            float acc;
            if (gx == 0)
                acc = fmaf(2.f * gw1, vp1, fmaf(2.f * gw0, vp2, gw2 * v));
            else if (gx == 1)
                acc = fmaf(gw1, vm1, fmaf(gw0 + gw2, v, fmaf(gw1, vp1, gw0 * vp2)));
            else if (gx == T_ - 2)
                acc = fmaf(gw0, vm2, fmaf(gw1, vm1, fmaf(gw2 + gw0, v, gw1 * vp1)));
            else if (gx == T_ - 1)
                acc = fmaf(2.f * gw0, vm2, fmaf(2.f * gw1, vm1, gw2 * v));
            else {
                float s0 = vm2 + vp2, s1 = vm1 + vp1;
                acc = fmaf(gw0, s0, fmaf(gw1, s1, gw2 * v));
            }
            op[(size_t)r * T_] = acc;
            bmx = fmaxf(bmx, acc); bmn = fminf(bmn, acc);
        }
    }

    // ---- Fused per-batch min/max of the blurred field ----
#pragma unroll
    for (int o = 16; o > 0; o >>= 1) {
        bmx = fmaxf(bmx, __shfl_xor_sync(0xffffffffu, bmx, o));
        bmn = fminf(bmn, __shfl_xor_sync(0xffffffffu, bmn, o));
    }
    if (lane == 0) { smx[w] = bmx; smn[w] = bmn; }
    __syncthreads();
    if (tid == 0) {
        bmx = smx[0]; bmn = smn[0];
#pragma unroll
        for (int i = 1; i < 5; i++) {
            bmx = fmaxf(bmx, smx[i]); bmn = fminf(bmn, smn[i]);
        }
        atomicMax(&g_mx2[b], fkey(bmx));
        atomicMin(&g_mn2[b], fkey(bmn));
    }
}

// Stage D: peak2 + ordered compaction of the first PADL positives per batch.
// One 1024-thread block per batch; early exit once 256 entries are placed.
__global__ __launch_bounds__(1024)
void extract_k(float* __restrict__ out) {
    const int b = blockIdx.x;
    const float* bl = g_blur + (size_t)b * NPB;
    const float mn2 = funkey(g_mn2[b]);
    const float rng2 = funkey(g_mx2[b]) - mn2;
    float* ob = out + b * 3 * PADL;
    const int tid = threadIdx.x;
    const int lane = tid & 31, w = tid >> 5;

    for (int i = tid; i < 3 * PADL; i += 1024) ob[i] = 0.f;

    __shared__ unsigned s_wc[32];
    __shared__ unsigned s_tot;
    __shared__ unsigned s_base;
    if (tid == 0) s_base = 0;
    __syncthreads();

    for (int chunk = 0; chunk < NPB / 1024; chunk++) {
        int idx = chunk * 1024 + tid;
        int y = idx >> 12;          // idx / T_
        int x = idx & (T_ - 1);
        float v  = bl[idx];
        float nU = (y > 0)      ? bl[idx - T_] : -INFINITY;
        float nD = (y < F_ - 1) ? bl[idx + T_] : -INFINITY;
        float nL = (x > 0)      ? bl[idx - 1]  : -INFINITY;
        float nR = (x < T_ - 1) ? bl[idx + 1]  : -INFINITY;
        bool m = (v >= nU) && (v >= nD) && (v >= nL) && (v >= nR);
        float val = m ? __fdiv_rn(v - mn2, rng2) : 0.f;
        bool pred = val > 0.f;

        unsigned bal = __ballot_sync(0xffffffffu, pred);
        if (lane == 0) s_wc[w] = (unsigned)__popc(bal);
        __syncthreads();
        if (tid == 0) {
            unsigned run = 0;
#pragma unroll
            for (int i = 0; i < 32; i++) { unsigned c = s_wc[i]; s_wc[i] = run; run += c; }
            s_tot = run;
        }
        __syncthreads();
        unsigned base = s_base;
        unsigned tot  = s_tot;
        if (pred) {
            unsigned slot = base + s_wc[w] + (unsigned)__popc(bal & ((1u << lane) - 1u));
            if (slot < PADL) {
                ob[slot]            = (float)y / (float)F_;
                ob[PADL + slot]     = (float)x / (float)T_;
                ob[2 * PADL + slot] = val;
            }
        }
        __syncthreads();
        if (tid == 0) s_base = base + tot;
        if (base + tot >= PADL) break;   // uniform decision
        __syncthreads();
    }
}

extern "C" void kernel_launch(void* const* d_in, const int* in_sizes, int n_in,
                              void* d_out, int out_size) {
    const float* in = (const float*)d_in[0];
    float* out = (float*)d_out;

    // Gaussian weights, fp32, same formula as the reference.
    float g[5];
    float s = 0.f;
    for (int i = 0; i < 5; i++) {
        float c = (float)(i - 2);
        g[i] = expf(-0.5f * c * c);
    }
    for (int i = 0; i < 5; i++) s += g[i];
    for (int i = 0; i < 5; i++) g[i] = g[i] / s;

    init_k<<<1, 32>>>();
    minmax1_k<<<dim3(64, B_), 256>>>(in);
    blur_k<<<dim3(T_ / TT, F_ / TF, B_), NTHR>>>(in, g[0], g[1], g[2]);
    extract_k<<<B_, 1024>>>(out);
}